// round 11
// baseline (speedup 1.0000x reference)
#include <cuda_runtime.h>

#define Nn 50000
#define Rr 16
#define Hh 32
#define Ll 8
#define Ee 1600000

// Scratch (static __device__ arrays: allocation-free per harness rules)
__device__ __align__(16) int   g_cnt[Rr * Nn];       // per-(relation,dst) edge counts
__device__ __align__(16) float g_enorm[Ee];          // per-edge 1/deg_r(dst) (layer1 writes)
__device__ __align__(16) float g_h1[Nn * Hh];        // layer-1 aggregation
__device__ __align__(16) float g_T[Nn * Rr * Ll];    // T[n][r][l] = (h1[n,:] @ W2[r])[l]

// Vector reduction: 4x fp32 add in one L2 atomic op (sm_90+)
__device__ __forceinline__ void red_add_v4(float* p, float4 v) {
    asm volatile("red.global.add.v4.f32 [%0], {%1,%2,%3,%4};"
                 :: "l"(p), "f"(v.x), "f"(v.y), "f"(v.z), "f"(v.w)
                 : "memory");
}

// Packed f32x2 ops (sm_103a)
__device__ __forceinline__ void fma_f32x2(unsigned long long& acc,
                                          unsigned long long a,
                                          unsigned long long b) {
    asm("fma.rn.f32x2 %0, %1, %2, %0;" : "+l"(acc) : "l"(a), "l"(b));
}
__device__ __forceinline__ unsigned long long add_f32x2(unsigned long long a,
                                                        unsigned long long b) {
    unsigned long long r;
    asm("add.rn.f32x2 %0, %1, %2;" : "=l"(r) : "l"(a), "l"(b));
    return r;
}
__device__ __forceinline__ unsigned long long pack_f32x2(float lo, float hi) {
    unsigned long long r;
    asm("mov.b64 %0, {%1, %2};" : "=l"(r) : "f"(lo), "f"(hi));
    return r;
}
__device__ __forceinline__ void unpack_f32x2(unsigned long long v, float& lo, float& hi) {
    asm("mov.b64 {%0, %1}, %2;" : "=f"(lo), "=f"(hi) : "l"(v));
}

// ---------------------------------------------------------------------------
// Zero accumulators (g_cnt, g_h1). out is initialized by k_T.
// ---------------------------------------------------------------------------
__global__ void k_zero() {
    int i = blockIdx.x * blockDim.x + threadIdx.x;
    int stride = gridDim.x * blockDim.x;
    float4 z = make_float4(0.f, 0.f, 0.f, 0.f);
    int4* c4 = (int4*)g_cnt;
    float4* h4 = (float4*)g_h1;
    for (int j = i; j < (Rr * Nn) / 4; j += stride) c4[j] = make_int4(0, 0, 0, 0);
    for (int j = i; j < (Nn * Hh) / 4; j += stride) h4[j] = z;
}

// ---------------------------------------------------------------------------
// Per-(relation,dst) edge counts. 8 edges per thread (MLP=8).
// ---------------------------------------------------------------------------
__global__ void k_count(const int* __restrict__ et, const int* __restrict__ dst) {
    int t = blockIdx.x * blockDim.x + threadIdx.x;
    if (t >= Ee / 8) return;
    int e0 = t * 8;
    int4 da = *(const int4*)(dst + e0);
    int4 db = *(const int4*)(dst + e0 + 4);
    int4 ra = *(const int4*)(et + e0);
    int4 rb = *(const int4*)(et + e0 + 4);
    atomicAdd(&g_cnt[ra.x * Nn + da.x], 1);
    atomicAdd(&g_cnt[ra.y * Nn + da.y], 1);
    atomicAdd(&g_cnt[ra.z * Nn + da.z], 1);
    atomicAdd(&g_cnt[ra.w * Nn + da.w], 1);
    atomicAdd(&g_cnt[rb.x * Nn + db.x], 1);
    atomicAdd(&g_cnt[rb.y * Nn + db.y], 1);
    atomicAdd(&g_cnt[rb.z * Nn + db.z], 1);
    atomicAdd(&g_cnt[rb.w * Nn + db.w], 1);
}

// ---------------------------------------------------------------------------
// Layer 1: 8 threads per edge (quarter-row each), 4 edges per thread.
//   norm = 1/max(cnt[r*N+d],1)   (inline gather; 8 lanes coalesce to 1 sector)
//   g_h1[dst, q*4..] += W1[r, src, q*4..] * norm
// Lane q==0 stores the 4 edge-norms to g_enorm for layer2 reuse.
// ---------------------------------------------------------------------------
__global__ void k_layer1(const int* __restrict__ src, const int* __restrict__ dst,
                         const int* __restrict__ et, const float* __restrict__ W1) {
    int g = blockIdx.x * blockDim.x + threadIdx.x;
    int grp = g >> 3;        // which edge-quad
    int q = g & 7;           // which quarter of the 32-wide row
    if (grp >= Ee / 4) return;
    int e0 = grp * 4;

    int4 s4 = *(const int4*)(src + e0);
    int4 d4 = *(const int4*)(dst + e0);
    int4 r4 = *(const int4*)(et + e0);
    int ss[4] = {s4.x, s4.y, s4.z, s4.w};
    int dd[4] = {d4.x, d4.y, d4.z, d4.w};
    int rr[4] = {r4.x, r4.y, r4.z, r4.w};

    float  nn[4];
    float4 ww[4];
#pragma unroll
    for (int k = 0; k < 4; k++) {
        nn[k] = 1.0f / fmaxf((float)__ldg(&g_cnt[rr[k] * Nn + dd[k]]), 1.0f);
        ww[k] = *(const float4*)(W1 + (rr[k] * Nn + ss[k]) * Hh + q * 4);
    }
    if (q == 0) {
        *(float4*)(g_enorm + e0) = make_float4(nn[0], nn[1], nn[2], nn[3]);
    }
#pragma unroll
    for (int k = 0; k < 4; k++) {
        float4 v = make_float4(ww[k].x * nn[k], ww[k].y * nn[k],
                               ww[k].z * nn[k], ww[k].w * nn[k]);
        red_add_v4(&g_h1[dd[k] * Hh + q * 4], v);
    }
}

// ---------------------------------------------------------------------------
// Fused k_T (register-weight GEMM, f32x2):
//   h = relu(agg + root1 + b1)   -> staged in shared as DUPLICATED (h,h) u64
//   T[n][r][l] = sum_h h[n,h] * W2[r,h,l]   (W2 slice = 32 u64 pairs in regs)
//   out[n,l]   = (h @ root2)[l] + b2[l]     (base for layer2 REDs)
// Block = 256 thr: 4 groups x 64 (r,lp) threads; tile = 32 nodes.
// Inner loop per node: 16 LDS.128 (2 dup-pairs each) + 32 FFMA2, 2 acc chains.
// ---------------------------------------------------------------------------
__global__ void k_T(const float* __restrict__ W2, const float* __restrict__ root1,
                    const float* __restrict__ b1, const float* __restrict__ root2,
                    const float* __restrict__ b2, float* __restrict__ out) {
    __shared__ unsigned long long sH2[32][34];  // [node][h] dup pairs, padded row
    __shared__ float sR[Hh * Ll];               // root2 [h][l]

    int tid = threadIdx.x;
    for (int i = tid; i < Hh * Ll; i += 256) sR[i] = root2[i];

    // W2 slice into registers as f32x2 pairs: thread owns (r, lp)
    int r  = (tid >> 2) & 15;
    int lp = tid & 3;
    int grp = tid >> 6;                  // 4 node-groups
    unsigned long long w[Hh];
#pragma unroll
    for (int hh = 0; hh < Hh; hh++) {
        float2 wv = *(const float2*)(W2 + (r * Hh + hh) * Ll + lp * 2);
        w[hh] = pack_f32x2(wv.x, wv.y);
    }

    // Phase A: stage relu(agg + root1 + b1) as duplicated pairs
    int tile = blockIdx.x;
    int gidx = tile * 1024 + tid * 4;    // float index into [n][h] arrays
    float4 hv = make_float4(0.f, 0.f, 0.f, 0.f);
    if (gidx < Nn * Hh) {
        float4 av = *(const float4*)(g_h1 + gidx);
        float4 rv = *(const float4*)(root1 + gidx);
        int h0 = (tid & 7) * 4;
        hv.x = fmaxf(av.x + rv.x + __ldg(b1 + h0 + 0), 0.0f);
        hv.y = fmaxf(av.y + rv.y + __ldg(b1 + h0 + 1), 0.0f);
        hv.z = fmaxf(av.z + rv.z + __ldg(b1 + h0 + 2), 0.0f);
        hv.w = fmaxf(av.w + rv.w + __ldg(b1 + h0 + 3), 0.0f);
    }
    {
        int node = tid >> 3;
        int h0 = (tid & 7) * 4;
        sH2[node][h0 + 0] = pack_f32x2(hv.x, hv.x);
        sH2[node][h0 + 1] = pack_f32x2(hv.y, hv.y);
        sH2[node][h0 + 2] = pack_f32x2(hv.z, hv.z);
        sH2[node][h0 + 3] = pack_f32x2(hv.w, hv.w);
    }
    __syncthreads();

    // Out-base: thread = (node_in_tile, l); read lo half of dup pair
    {
        int node = tid >> 3;
        int l = tid & 7;
        int n = tile * 32 + node;
        if (n < Nn) {
            float y = __ldg(b2 + l);
#pragma unroll
            for (int hh = 0; hh < Hh; hh++) {
                float hval = *(const float*)&sH2[node][hh];
                y += hval * sR[hh * Ll + l];
            }
            out[n * Ll + l] = y;
        }
    }

    // Main: each (grp, r, lp) thread handles 8 nodes; 2 accumulator chains
#pragma unroll
    for (int i = 0; i < 8; i++) {
        int ni = grp * 8 + i;
        int n = tile * 32 + ni;
        if (n >= Nn) break;
        unsigned long long acc0 = pack_f32x2(0.f, 0.f);
        unsigned long long acc1 = pack_f32x2(0.f, 0.f);
        const ulonglong2* hp = (const ulonglong2*)&sH2[ni][0];
#pragma unroll
        for (int j = 0; j < 16; j++) {
            ulonglong2 p = hp[j];                 // LDS.128: 2 dup-pairs (broadcast)
            fma_f32x2(acc0, p.x, w[2 * j]);
            fma_f32x2(acc1, p.y, w[2 * j + 1]);
        }
        unsigned long long acc = add_f32x2(acc0, acc1);
        float lo, hi;
        unpack_f32x2(acc, lo, hi);
        *(float2*)(g_T + (n * Rr + r) * Ll + lp * 2) = make_float2(lo, hi);
    }
}

// ---------------------------------------------------------------------------
// Layer 2 edge pass: 2 threads per edge (half-row each), 8 edges per thread.
//   out[dst, half*4..] += enorm[e] * T[src][r][half*4..]
// ---------------------------------------------------------------------------
__global__ void k_layer2(const int* __restrict__ src, const int* __restrict__ dst,
                         const int* __restrict__ et, float* __restrict__ out) {
    int g = blockIdx.x * blockDim.x + threadIdx.x;
    int oct = g >> 1;
    int half = g & 1;
    if (oct >= Ee / 8) return;
    int e0 = oct * 8;

    int4 sa = *(const int4*)(src + e0);
    int4 sb = *(const int4*)(src + e0 + 4);
    int4 da = *(const int4*)(dst + e0);
    int4 db = *(const int4*)(dst + e0 + 4);
    int4 ra = *(const int4*)(et + e0);
    int4 rb = *(const int4*)(et + e0 + 4);
    float4 na = *(const float4*)(g_enorm + e0);
    float4 nb = *(const float4*)(g_enorm + e0 + 4);
    int ss[8] = {sa.x, sa.y, sa.z, sa.w, sb.x, sb.y, sb.z, sb.w};
    int dd[8] = {da.x, da.y, da.z, da.w, db.x, db.y, db.z, db.w};
    int rr[8] = {ra.x, ra.y, ra.z, ra.w, rb.x, rb.y, rb.z, rb.w};
    float nn[8] = {na.x, na.y, na.z, na.w, nb.x, nb.y, nb.z, nb.w};

    float4 tv[8];
#pragma unroll
    for (int k = 0; k < 8; k++) {
        tv[k] = *(const float4*)(g_T + (ss[k] * Rr + rr[k]) * Ll + half * 4);
    }
#pragma unroll
    for (int k = 0; k < 8; k++) {
        float4 v = make_float4(tv[k].x * nn[k], tv[k].y * nn[k],
                               tv[k].z * nn[k], tv[k].w * nn[k]);
        red_add_v4(&out[dd[k] * Ll + half * 4], v);
    }
}

// ---------------------------------------------------------------------------
// Final: out = sigmoid(out), elementwise
// ---------------------------------------------------------------------------
__global__ void k_final(float* __restrict__ out) {
    int i = blockIdx.x * blockDim.x + threadIdx.x;
    if (i >= (Nn * Ll) / 4) return;
    float4 v = ((const float4*)out)[i];
    v.x = 1.0f / (1.0f + expf(-v.x));
    v.y = 1.0f / (1.0f + expf(-v.y));
    v.z = 1.0f / (1.0f + expf(-v.z));
    v.w = 1.0f / (1.0f + expf(-v.w));
    ((float4*)out)[i] = v;
}

// ---------------------------------------------------------------------------
extern "C" void kernel_launch(void* const* d_in, const int* in_sizes, int n_in,
                              void* d_out, int out_size) {
    const int* ei    = (const int*)d_in[0];    // edge_index [2, E]
    const int* et    = (const int*)d_in[1];    // edge_type  [E]
    const float* W1  = (const float*)d_in[2];  // [R, N, H]
    const float* rt1 = (const float*)d_in[3];  // [N, H]
    const float* b1  = (const float*)d_in[4];  // [H]
    const float* W2  = (const float*)d_in[5];  // [R, H, L]
    const float* rt2 = (const float*)d_in[6];  // [H, L]
    const float* b2  = (const float*)d_in[7];  // [L]
    float* out = (float*)d_out;                // [N, L]

    const int* src = ei;
    const int* dst = ei + Ee;

    k_zero<<<1024, 256>>>();
    k_count<<<(Ee / 8 + 255) / 256, 256>>>(et, dst);
    k_layer1<<<(Ee / 4) * 8 / 256, 256>>>(src, dst, et, W1);     // 8 thr/edge, 4 edges/thr
    k_T<<<(Nn + 31) / 32, 256>>>(W2, rt1, b1, rt2, b2, out);     // f32x2 register-weight GEMM
    k_layer2<<<((Ee / 8) * 2 + 255) / 256, 256>>>(src, dst, et, out); // 2 thr/edge, 8 edges/thr
    k_final<<<((Nn * Ll) / 4 + 255) / 256, 256>>>(out);
}

// round 12
// speedup vs baseline: 1.0023x; 1.0023x over previous
#include <cuda_runtime.h>

#define Nn 50000
#define Rr 16
#define Hh 32
#define Ll 8
#define Ee 1600000

// Scratch (static __device__ arrays: allocation-free per harness rules)
__device__ __align__(16) int   g_cnt[Rr * Nn];       // per-(relation,dst) edge counts
__device__ __align__(16) float g_enorm[Ee];          // per-edge 1/deg_r(dst) (layer1 writes)
__device__ __align__(16) float g_h1[Nn * Hh];        // layer-1 aggregation
__device__ __align__(16) float g_T[Nn * Rr * Ll];    // T[n][r][l] = (h1[n,:] @ W2[r])[l]

// Vector reduction: 4x fp32 add in one L2 atomic op (sm_90+)
__device__ __forceinline__ void red_add_v4(float* p, float4 v) {
    asm volatile("red.global.add.v4.f32 [%0], {%1,%2,%3,%4};"
                 :: "l"(p), "f"(v.x), "f"(v.y), "f"(v.z), "f"(v.w)
                 : "memory");
}

// ---------------------------------------------------------------------------
// Zero accumulators (g_cnt, g_h1). out is initialized by k_T.
// ---------------------------------------------------------------------------
__global__ void k_zero() {
    int i = blockIdx.x * blockDim.x + threadIdx.x;
    int stride = gridDim.x * blockDim.x;
    float4 z = make_float4(0.f, 0.f, 0.f, 0.f);
    int4* c4 = (int4*)g_cnt;
    float4* h4 = (float4*)g_h1;
    for (int j = i; j < (Rr * Nn) / 4; j += stride) c4[j] = make_int4(0, 0, 0, 0);
    for (int j = i; j < (Nn * Hh) / 4; j += stride) h4[j] = z;
}

// ---------------------------------------------------------------------------
// Per-(relation,dst) edge counts. 8 edges per thread (MLP=8).
// ---------------------------------------------------------------------------
__global__ void k_count(const int* __restrict__ et, const int* __restrict__ dst) {
    int t = blockIdx.x * blockDim.x + threadIdx.x;
    if (t >= Ee / 8) return;
    int e0 = t * 8;
    int4 da = *(const int4*)(dst + e0);
    int4 db = *(const int4*)(dst + e0 + 4);
    int4 ra = *(const int4*)(et + e0);
    int4 rb = *(const int4*)(et + e0 + 4);
    atomicAdd(&g_cnt[ra.x * Nn + da.x], 1);
    atomicAdd(&g_cnt[ra.y * Nn + da.y], 1);
    atomicAdd(&g_cnt[ra.z * Nn + da.z], 1);
    atomicAdd(&g_cnt[ra.w * Nn + da.w], 1);
    atomicAdd(&g_cnt[rb.x * Nn + db.x], 1);
    atomicAdd(&g_cnt[rb.y * Nn + db.y], 1);
    atomicAdd(&g_cnt[rb.z * Nn + db.z], 1);
    atomicAdd(&g_cnt[rb.w * Nn + db.w], 1);
}

// ---------------------------------------------------------------------------
// Layer 1: 8 threads per edge (quarter-row each), 4 edges per thread.
//   norm = 1/max(cnt[r*N+d],1)   (inline gather)
//   g_h1[dst, q*4..] += W1[r, src, q*4..] * norm
// Lane q==0 stores the 4 edge-norms to g_enorm for layer2 reuse.
// ---------------------------------------------------------------------------
__global__ void k_layer1(const int* __restrict__ src, const int* __restrict__ dst,
                         const int* __restrict__ et, const float* __restrict__ W1) {
    int g = blockIdx.x * blockDim.x + threadIdx.x;
    int grp = g >> 3;        // which edge-quad
    int q = g & 7;           // which quarter of the 32-wide row
    if (grp >= Ee / 4) return;
    int e0 = grp * 4;

    int4 s4 = *(const int4*)(src + e0);
    int4 d4 = *(const int4*)(dst + e0);
    int4 r4 = *(const int4*)(et + e0);
    int ss[4] = {s4.x, s4.y, s4.z, s4.w};
    int dd[4] = {d4.x, d4.y, d4.z, d4.w};
    int rr[4] = {r4.x, r4.y, r4.z, r4.w};

    float  nn[4];
    float4 ww[4];
#pragma unroll
    for (int k = 0; k < 4; k++) {
        nn[k] = 1.0f / fmaxf((float)__ldg(&g_cnt[rr[k] * Nn + dd[k]]), 1.0f);
        ww[k] = *(const float4*)(W1 + (rr[k] * Nn + ss[k]) * Hh + q * 4);
    }
    if (q == 0) {
        *(float4*)(g_enorm + e0) = make_float4(nn[0], nn[1], nn[2], nn[3]);
    }
#pragma unroll
    for (int k = 0; k < 4; k++) {
        float4 v = make_float4(ww[k].x * nn[k], ww[k].y * nn[k],
                               ww[k].z * nn[k], ww[k].w * nn[k]);
        red_add_v4(&g_h1[dd[k] * Hh + q * 4], v);
    }
}

// ---------------------------------------------------------------------------
// Fused k_T (register-weight GEMM, 1 output column per thread):
//   h = relu(agg + root1 + b1)                       (staged in 4KB shared/tile)
//   T[n][r][l] = sum_h h[n,h] * W2[r,h,l]            (w column = 32 REGISTERS)
//   out[n,l]   = (h @ root2)[l] + b2[l]              (base for layer2 REDs)
// Block = 512 thr: 4 groups x 128 (r,l) threads; tile = 32 nodes, 8 per group.
// Per node per thread: 8 broadcast LDS.128 + 32 FFMA + 1 coalesced STG.32
// (warp = 4 r x 8 l -> 32 consecutive floats of T[n]).
// ---------------------------------------------------------------------------
__global__ void __launch_bounds__(512, 2)
k_T(const float* __restrict__ W2, const float* __restrict__ root1,
    const float* __restrict__ b1, const float* __restrict__ root2,
    const float* __restrict__ b2, float* __restrict__ out) {
    __shared__ float4 sH[256];           // 32 nodes x 32 h  (sH[node*8+j])
    __shared__ float  sR[Hh * Ll];       // root2 [h][l]

    int tid = threadIdx.x;
    for (int i = tid; i < Hh * Ll; i += 512) sR[i] = root2[i];

    // W2 column into registers: thread owns (r, l) -> W2[r][0..31][l]
    int rl  = tid & 127;                 // r*8 + l
    int r   = rl >> 3;
    int l   = rl & 7;
    int grp = tid >> 7;                  // 4 node-groups
    float w[Hh];
#pragma unroll
    for (int hh = 0; hh < Hh; hh++)
        w[hh] = __ldg(W2 + (r * Hh + hh) * Ll + l);

    // Phase A: stage relu(agg + root1 + b1) for 32 nodes (first 256 threads)
    int tile = blockIdx.x;
    if (tid < 256) {
        int gidx = tile * 1024 + tid * 4;    // float index into [n][h] arrays
        float4 hv = make_float4(0.f, 0.f, 0.f, 0.f);
        if (gidx < Nn * Hh) {
            float4 av = *(const float4*)(g_h1 + gidx);
            float4 rv = *(const float4*)(root1 + gidx);
            int h0 = (tid & 7) * 4;
            hv.x = fmaxf(av.x + rv.x + __ldg(b1 + h0 + 0), 0.0f);
            hv.y = fmaxf(av.y + rv.y + __ldg(b1 + h0 + 1), 0.0f);
            hv.z = fmaxf(av.z + rv.z + __ldg(b1 + h0 + 2), 0.0f);
            hv.w = fmaxf(av.w + rv.w + __ldg(b1 + h0 + 3), 0.0f);
        }
        sH[tid] = hv;
    }
    __syncthreads();

    // Out-base (first 256 threads): thread = (node_in_tile, l)
    if (tid < 256) {
        int node = tid >> 3;
        int lo = tid & 7;
        int n = tile * 32 + node;
        if (n < Nn) {
            const float* sHf = (const float*)sH;
            float y = __ldg(b2 + lo);
#pragma unroll
            for (int hh = 0; hh < Hh; hh++)
                y += sHf[node * Hh + hh] * sR[hh * Ll + lo];
            out[n * Ll + lo] = y;
        }
    }

    // Main: each (grp, r, l) thread handles 8 nodes
#pragma unroll
    for (int i = 0; i < 8; i++) {
        int ni = grp * 8 + i;
        int n = tile * 32 + ni;
        if (n >= Nn) break;
        float a0 = 0.0f, a1 = 0.0f, a2 = 0.0f, a3 = 0.0f;
#pragma unroll
        for (int j = 0; j < 8; j++) {
            float4 h4 = sH[ni * 8 + j];          // broadcast LDS.128
            a0 += h4.x * w[j * 4 + 0];
            a1 += h4.y * w[j * 4 + 1];
            a2 += h4.z * w[j * 4 + 2];
            a3 += h4.w * w[j * 4 + 3];
        }
        g_T[n * (Rr * Ll) + rl] = (a0 + a1) + (a2 + a3);
    }
}

// ---------------------------------------------------------------------------
// Layer 2 edge pass: 2 threads per edge (half-row each), 8 edges per thread.
//   out[dst, half*4..] += enorm[e] * T[src][r][half*4..]
// ---------------------------------------------------------------------------
__global__ void k_layer2(const int* __restrict__ src, const int* __restrict__ dst,
                         const int* __restrict__ et, float* __restrict__ out) {
    int g = blockIdx.x * blockDim.x + threadIdx.x;
    int oct = g >> 1;
    int half = g & 1;
    if (oct >= Ee / 8) return;
    int e0 = oct * 8;

    int4 sa = *(const int4*)(src + e0);
    int4 sb = *(const int4*)(src + e0 + 4);
    int4 da = *(const int4*)(dst + e0);
    int4 db = *(const int4*)(dst + e0 + 4);
    int4 ra = *(const int4*)(et + e0);
    int4 rb = *(const int4*)(et + e0 + 4);
    float4 na = *(const float4*)(g_enorm + e0);
    float4 nb = *(const float4*)(g_enorm + e0 + 4);
    int ss[8] = {sa.x, sa.y, sa.z, sa.w, sb.x, sb.y, sb.z, sb.w};
    int dd[8] = {da.x, da.y, da.z, da.w, db.x, db.y, db.z, db.w};
    int rr[8] = {ra.x, ra.y, ra.z, ra.w, rb.x, rb.y, rb.z, rb.w};
    float nn[8] = {na.x, na.y, na.z, na.w, nb.x, nb.y, nb.z, nb.w};

    float4 tv[8];
#pragma unroll
    for (int k = 0; k < 8; k++) {
        tv[k] = *(const float4*)(g_T + (ss[k] * Rr + rr[k]) * Ll + half * 4);
    }
#pragma unroll
    for (int k = 0; k < 8; k++) {
        float4 v = make_float4(tv[k].x * nn[k], tv[k].y * nn[k],
                               tv[k].z * nn[k], tv[k].w * nn[k]);
        red_add_v4(&out[dd[k] * Ll + half * 4], v);
    }
}

// ---------------------------------------------------------------------------
// Final: out = sigmoid(out), elementwise
// ---------------------------------------------------------------------------
__global__ void k_final(float* __restrict__ out) {
    int i = blockIdx.x * blockDim.x + threadIdx.x;
    if (i >= (Nn * Ll) / 4) return;
    float4 v = ((const float4*)out)[i];
    v.x = 1.0f / (1.0f + expf(-v.x));
    v.y = 1.0f / (1.0f + expf(-v.y));
    v.z = 1.0f / (1.0f + expf(-v.z));
    v.w = 1.0f / (1.0f + expf(-v.w));
    ((float4*)out)[i] = v;
}

// ---------------------------------------------------------------------------
extern "C" void kernel_launch(void* const* d_in, const int* in_sizes, int n_in,
                              void* d_out, int out_size) {
    const int* ei    = (const int*)d_in[0];    // edge_index [2, E]
    const int* et    = (const int*)d_in[1];    // edge_type  [E]
    const float* W1  = (const float*)d_in[2];  // [R, N, H]
    const float* rt1 = (const float*)d_in[3];  // [N, H]
    const float* b1  = (const float*)d_in[4];  // [H]
    const float* W2  = (const float*)d_in[5];  // [R, H, L]
    const float* rt2 = (const float*)d_in[6];  // [H, L]
    const float* b2  = (const float*)d_in[7];  // [L]
    float* out = (float*)d_out;                // [N, L]

    const int* src = ei;
    const int* dst = ei + Ee;

    k_zero<<<1024, 256>>>();
    k_count<<<(Ee / 8 + 255) / 256, 256>>>(et, dst);
    k_layer1<<<(Ee / 4) * 8 / 256, 256>>>(src, dst, et, W1);     // 8 thr/edge, 4 edges/thr
    k_T<<<(Nn + 31) / 32, 512>>>(W2, rt1, b1, rt2, b2, out);     // 1 col/thread, 32 w-regs
    k_layer2<<<((Ee / 8) * 2 + 255) / 256, 256>>>(src, dst, et, out); // 2 thr/edge, 8 edges/thr
    k_final<<<((Nn * Ll) / 4 + 255) / 256, 256>>>(out);
}